// round 1
// baseline (speedup 1.0000x reference)
#include <cuda_runtime.h>
#include <cstdint>

// LinearPositionInterpolation:
//   index: (n,) int32 sorted keypoints (n=129, spacing 32 in this dataset)
//   value: (batch, n, dim) fp32   (32, 129, 256)
//   out:   (batch, m, dim) fp32 with m = index[n-1]-index[0]  (32, 4096, 256)
// out[b, p-1, d] = y0 + (y1-y0)*w,  seg = searchsorted(idx, p, 'left')-1,
//   w = (p - idx[seg]) / (idx[seg+1] - idx[seg]),  p in [1, m]
//
// HBM-write-bound: 134 MB out, 4.2 MB value (L2-resident). Vectorized float4.

#ifndef DIM_GUESS
#define DIM_GUESS 256
#endif

__global__ void lpi_kernel(const int* __restrict__ index,
                           const float4* __restrict__ value,
                           float4* __restrict__ out,
                           int n, int m, int dim4, long long total4)
{
    // Cache keypoint positions in shared memory (n <= 512 assumed; n=129 here).
    __shared__ int sidx[512];
    for (int i = threadIdx.x; i < n; i += blockDim.x)
        sidx[i] = index[i];
    __syncthreads();

    long long id = (long long)blockIdx.x * blockDim.x + threadIdx.x;
    if (id >= total4) return;

    const int base = sidx[0];

    int d       = (int)(id % dim4);
    long long r = id / dim4;
    int p       = (int)(r % m) + 1;     // position 1..m
    int b       = (int)(r / m);

    // lower_bound: first pos with (sidx[pos]-base) >= p, then seg = pos-1.
    // Warp-uniform (64 consecutive threads share p) -> no divergence.
    int lo = 0, hi = n - 1;
    #pragma unroll 4
    while (lo < hi) {
        int mid = (lo + hi) >> 1;
        if (sidx[mid] - base >= p) hi = mid; else lo = mid + 1;
    }
    int seg = lo - 1;
    int x0 = sidx[seg]     - base;
    int x1 = sidx[seg + 1] - base;
    float w = (float)(p - x0) / (float)(x1 - x0);

    long long vrow = ((long long)b * n + seg) * dim4 + d;
    float4 y0 = value[vrow];
    float4 y1 = value[vrow + dim4];

    float4 o;
    o.x = fmaf(y1.x - y0.x, w, y0.x);
    o.y = fmaf(y1.y - y0.y, w, y0.y);
    o.z = fmaf(y1.z - y0.z, w, y0.z);
    o.w = fmaf(y1.w - y0.w, w, y0.w);
    out[id] = o;
}

extern "C" void kernel_launch(void* const* d_in, const int* in_sizes, int n_in,
                              void* d_out, int out_size)
{
    const int*   index = (const int*)d_in[0];
    const float* value = (const float*)d_in[1];
    float*       outp  = (float*)d_out;

    int n = in_sizes[0];                       // 129
    int dim = DIM_GUESS;                       // 256 (fixed for this dataset)
    long long velems = in_sizes[1];
    int batch = (int)(velems / ((long long)n * dim));   // 32
    int m = (int)((long long)out_size / ((long long)batch * dim)); // 4096

    int dim4 = dim / 4;
    long long total4 = (long long)out_size / 4;

    const int BLOCK = 256;
    long long grid = (total4 + BLOCK - 1) / BLOCK;

    lpi_kernel<<<(unsigned)grid, BLOCK>>>(index,
                                          (const float4*)value,
                                          (float4*)outp,
                                          n, m, dim4, total4);
}

// round 2
// speedup vs baseline: 2.4547x; 2.4547x over previous
#include <cuda_runtime.h>
#include <cstdint>

// LinearPositionInterpolation — segment-parallel formulation.
//   index: (n,) int32 sorted keypoints (n=129, uniform spacing 32 here)
//   value: (batch, n, dim) fp32   (32, 129, 256)
//   out:   (batch, m, dim) fp32, m = index[n-1]-index[0] = 4096
//
// R1 post-mortem: previous kernel was issue/ALU-bound (issue 84%, DRAM 16%)
// due to 64-bit div/mod + binary search per 16B store. This version assigns
// one CTA per (segment, batch): y0/y1/dy/invL computed ONCE, then the 32
// output rows of the segment are streamed with ~6 instr per float4 store.
//
// dim = 256 is fixed for this dataset (compile-time so index math is
// shifts/masks).

#define DIM    256
#define DIM4   (DIM / 4)          // 64 float4 columns per row
#define ROWS   4                  // row-groups per CTA (blockDim = ROWS*DIM4)

__global__ __launch_bounds__(ROWS * DIM4)
void lpi_seg_kernel(const int* __restrict__ index,
                    const float4* __restrict__ value,
                    float4* __restrict__ out,
                    int n, int m)
{
    const int s  = blockIdx.x;            // segment id, 0..n-2
    const int b  = blockIdx.y;            // batch id
    const int d  = threadIdx.x & (DIM4 - 1);   // float4 column 0..63
    const int rg = threadIdx.x >> 6;           // row-group 0..ROWS-1

    const int base = __ldg(&index[0]);
    const int x0   = __ldg(&index[s])     - base;
    const int x1   = __ldg(&index[s + 1]) - base;
    const float invL = 1.0f / (float)(x1 - x0);

    // Keypoint rows for this segment (broadcast within block; L1/L2 resident).
    const long long vrow = ((long long)b * n + s) * DIM4 + d;
    const float4 y0 = value[vrow];
    const float4 y1 = value[vrow + DIM4];
    const float4 dy = make_float4(y1.x - y0.x, y1.y - y0.y,
                                  y1.z - y0.z, y1.w - y0.w);

    // Output rows for positions p = x0+1 .. x1  (out row = p-1).
    // Row-group rg handles p = x0+1+rg, stepping by ROWS.
    long long orow = ((long long)b * m + x0 + rg) * DIM4 + d;
    const long long ostep = (long long)ROWS * DIM4;

    for (int p = x0 + 1 + rg; p <= x1; p += ROWS) {
        const float w = (float)(p - x0) * invL;
        float4 o;
        o.x = fmaf(dy.x, w, y0.x);
        o.y = fmaf(dy.y, w, y0.y);
        o.z = fmaf(dy.z, w, y0.z);
        o.w = fmaf(dy.w, w, y0.w);
        out[orow] = o;
        orow += ostep;
    }
}

extern "C" void kernel_launch(void* const* d_in, const int* in_sizes, int n_in,
                              void* d_out, int out_size)
{
    const int*   index = (const int*)d_in[0];
    const float* value = (const float*)d_in[1];
    float*       outp  = (float*)d_out;

    int n = in_sizes[0];                                   // 129
    long long velems = in_sizes[1];
    int batch = (int)(velems / ((long long)n * DIM));      // 32
    int m = (int)((long long)out_size / ((long long)batch * DIM)); // 4096

    dim3 grid(n - 1, batch);             // (128, 32) = 4096 CTAs
    dim3 block(ROWS * DIM4);             // 256 threads

    lpi_seg_kernel<<<grid, block>>>(index,
                                    (const float4*)value,
                                    (float4*)outp,
                                    n, m);
}